// round 6
// baseline (speedup 1.0000x reference)
#include <cuda_runtime.h>

#define Bc 8
#define Cc 96
#define Hc 256
#define Wc 256
#define TH 8
#define RROWS 16               // raw rows: img rowBase-4 .. rowBase+11
#define VRS 10                 // bp/hp rows: img rowBase-1 .. rowBase+8
#define NQ 66
#define QS 67
#define FULLM 0xffffffffu

__device__ __forceinline__ float4 f4add(float4 a, float4 b) {
    return make_float4(a.x+b.x, a.y+b.y, a.z+b.z, a.w+b.w);
}
__device__ __forceinline__ float4 f4sub(float4 a, float4 b) {
    return make_float4(a.x-b.x, a.y-b.y, a.z-b.z, a.w-b.w);
}

__device__ __forceinline__ float rcnt0(int i, int p) {
    if (i < 0 || i > Hc - 1) return 0.f;
    int lo = i - p; if (lo < 0) lo = 0;
    int hi = i + p; if (hi > Hc - 1) hi = Hc - 1;
    return __fdividef(1.f, (float)(hi - lo + 1));
}

__device__ __forceinline__ float bn_silu(float acc, float scal, float shft) {
    float v = fmaf(acc, scal, shft);
    return v * __fdividef(1.f, 1.f + __expf(-v));
}

// 3x3 conv over buffer rows s0..s0+3 (VRS-slot space), shfl horizontal halo.
// Outputs 2 global rows: gy0, gy0+1.
__device__ __forceinline__ void conv3_shfl(const float4* __restrict__ buf, int s0,
                                           int q, bool eL, bool eR,
                                           const float* __restrict__ sw,
                                           float inv, float shft,
                                           float* __restrict__ outp, int gy0) {
    float w[9];
#pragma unroll
    for (int i = 0; i < 9; i++) w[i] = sw[i];
    float a0[4] = {0.f,0.f,0.f,0.f}, a1[4] = {0.f,0.f,0.f,0.f};
#pragma unroll
    for (int srel = 0; srel < 4; srel++) {
        const float4* rp = buf + (s0 + srel) * QS + q;
        float4 c = rp[0];
        float lw = __shfl_up_sync(FULLM, c.w, 4);
        float rw = __shfl_down_sync(FULLM, c.x, 4);
        if (eL) lw = ((const float*)(rp - 1))[3];
        if (eR) rw = ((const float*)(rp + 1))[0];
        float cols[6] = {lw, c.x, c.y, c.z, c.w, rw};
        if (srel < 3) {
#pragma unroll
            for (int kc = 0; kc < 3; kc++) {
                float wv = w[srel * 3 + kc];
#pragma unroll
                for (int p = 0; p < 4; p++) a0[p] = fmaf(wv, cols[p + kc], a0[p]);
            }
        }
        if (srel >= 1) {
#pragma unroll
            for (int kc = 0; kc < 3; kc++) {
                float wv = w[(srel - 1) * 3 + kc];
#pragma unroll
                for (int p = 0; p < 4; p++) a1[p] = fmaf(wv, cols[p + kc], a1[p]);
            }
        }
    }
    float4 o;
    o.x = bn_silu(a0[0], inv, shft); o.y = bn_silu(a0[1], inv, shft);
    o.z = bn_silu(a0[2], inv, shft); o.w = bn_silu(a0[3], inv, shft);
    *(float4*)(outp + (size_t)gy0 * Wc) = o;
    o.x = bn_silu(a1[0], inv, shft); o.y = bn_silu(a1[1], inv, shft);
    o.z = bn_silu(a1[2], inv, shft); o.w = bn_silu(a1[3], inv, shft);
    *(float4*)(outp + (size_t)(gy0 + 1) * Wc) = o;
}

__global__ __launch_bounds__(256, 5) void trifreq_kernel(
    const float* __restrict__ x,
    const float* __restrict__ w_lo,
    const float* __restrict__ w_mf,
    const float* __restrict__ w_hf,
    const float* __restrict__ bn_gamma,
    const float* __restrict__ bn_beta,
    const float* __restrict__ bn_mean,
    const float* __restrict__ bn_var,
    float* __restrict__ out)
{
    __shared__ float4 s_raw[RROWS * QS];
    __shared__ float4 s_v3[VRS * QS];    // mf: vertical 3-sums; hf: high-pass buffer
    __shared__ float4 s_v7[VRS * QS];    // mf: vertical 7-sums
    __shared__ float s_w[25];

    const int t = threadIdx.x;
    const int tileY = blockIdx.x;
    const int ch = blockIdx.y;
    const int b = blockIdx.z;
    const int group = ch >> 5;
    const int k = ch & 31;
    const int rowBase = tileY * TH;

    if (group == 0)      { if (t < 25) s_w[t] = w_lo[k * 25 + t]; }
    else if (group == 1) { if (t < 9)  s_w[t] = w_mf[k * 9 + t]; }
    else                 { if (t < 9)  s_w[t] = w_hf[k * 9 + t]; }

    // ---- raw tile load (zero outside image) ----
    const float* xp = x + (size_t)(b * Cc + ch) * Hc * Wc;
    const int rlo = (group == 0) ? 2 : 0;
    const int rhi = (group == 0) ? 14 : 16;
    const int nload = (rhi - rlo) * NQ;
    for (int idx = t; idx < nload; idx += 256) {
        int rr = idx / NQ + rlo;
        int qq = idx - (rr - rlo) * NQ;
        int gr = rowBase + rr - 4;
        float4 v = make_float4(0.f, 0.f, 0.f, 0.f);
        if (qq >= 1 && qq <= 64 && (unsigned)gr < (unsigned)Hc)
            v = *(const float4*)(xp + gr * Wc + (qq - 1) * 4);
        s_raw[rr * QS + qq] = v;
    }
    __syncthreads();

    const int oc = 3 * k + group;
    const float inv  = bn_gamma[oc] * rsqrtf(bn_var[oc] + 1e-5f);
    const float shft = bn_beta[oc] - bn_mean[oc] * inv;

    const int j = t >> 2;          // quad 0..63 (output cols 4j..4j+3)
    const int rc = t & 3;          // row slot
    const int q = j + 1;
    const int lane = t & 31;
    const bool eL = (lane < 4);    // j == 8w  : left neighbor cross-warp
    const bool eR = (lane >= 28);  // j == 8w+7: right neighbor cross-warp
    float* outp = out + (size_t)(b * Cc + oc) * Hc * Wc + j * 4;
    const int gyOut = rowBase + 2 * rc;     // first of the 2 output rows

    if (group == 0) {
        // ===== lo: 5x5 dwconv, shfl halo, two weight passes, rows gyOut..gyOut+1 =====
        float a0[4] = {0.f,0.f,0.f,0.f}, a1[4] = {0.f,0.f,0.f,0.f};
        const int s0 = 2 * rc + 2;
        {
            float wr[15];
#pragma unroll
            for (int i = 0; i < 15; i++) wr[i] = s_w[i];
#pragma unroll
            for (int srel = 0; srel < 4; srel++) {
                const float4* rp = s_raw + (s0 + srel) * QS + q;
                float4 c = rp[0];
                float l1 = __shfl_up_sync(FULLM, c.z, 4);
                float l2 = __shfl_up_sync(FULLM, c.w, 4);
                float r1 = __shfl_down_sync(FULLM, c.x, 4);
                float r2 = __shfl_down_sync(FULLM, c.y, 4);
                if (eL) { const float* p = (const float*)(rp - 1); l1 = p[2]; l2 = p[3]; }
                if (eR) { const float* p = (const float*)(rp + 1); r1 = p[0]; r2 = p[1]; }
                float cols[8] = {l1, l2, c.x, c.y, c.z, c.w, r1, r2};
                if (srel < 3) {
#pragma unroll
                    for (int kc = 0; kc < 5; kc++) {
                        float wv = wr[srel * 5 + kc];
#pragma unroll
                        for (int p = 0; p < 4; p++) a0[p] = fmaf(wv, cols[p + kc], a0[p]);
                    }
                }
                if (srel >= 1) {
#pragma unroll
                    for (int kc = 0; kc < 5; kc++) {
                        float wv = wr[(srel - 1) * 5 + kc];
#pragma unroll
                        for (int p = 0; p < 4; p++) a1[p] = fmaf(wv, cols[p + kc], a1[p]);
                    }
                }
            }
        }
        {
            float wr[10];
#pragma unroll
            for (int i = 0; i < 10; i++) wr[i] = s_w[15 + i];
#pragma unroll
            for (int srel = 3; srel < 6; srel++) {
                const float4* rp = s_raw + (s0 + srel) * QS + q;
                float4 c = rp[0];
                float l1 = __shfl_up_sync(FULLM, c.z, 4);
                float l2 = __shfl_up_sync(FULLM, c.w, 4);
                float r1 = __shfl_down_sync(FULLM, c.x, 4);
                float r2 = __shfl_down_sync(FULLM, c.y, 4);
                if (eL) { const float* p = (const float*)(rp - 1); l1 = p[2]; l2 = p[3]; }
                if (eR) { const float* p = (const float*)(rp + 1); r1 = p[0]; r2 = p[1]; }
                float cols[8] = {l1, l2, c.x, c.y, c.z, c.w, r1, r2};
                if (srel <= 4) {                 // o=0, kr = srel in {3,4}
#pragma unroll
                    for (int kc = 0; kc < 5; kc++) {
                        float wv = wr[(srel - 3) * 5 + kc];
#pragma unroll
                        for (int p = 0; p < 4; p++) a0[p] = fmaf(wv, cols[p + kc], a0[p]);
                    }
                }
                if (srel >= 4) {                 // o=1, kr = srel-1 in {3,4}
#pragma unroll
                    for (int kc = 0; kc < 5; kc++) {
                        float wv = wr[(srel - 4) * 5 + kc];
#pragma unroll
                        for (int p = 0; p < 4; p++) a1[p] = fmaf(wv, cols[p + kc], a1[p]);
                    }
                }
            }
        }
        float4 o;
        o.x = bn_silu(a0[0], inv, shft); o.y = bn_silu(a0[1], inv, shft);
        o.z = bn_silu(a0[2], inv, shft); o.w = bn_silu(a0[3], inv, shft);
        *(float4*)(outp + (size_t)gyOut * Wc) = o;
        o.x = bn_silu(a1[0], inv, shft); o.y = bn_silu(a1[1], inv, shft);
        o.z = bn_silu(a1[2], inv, shft); o.w = bn_silu(a1[3], inv, shft);
        *(float4*)(outp + (size_t)(gyOut + 1) * Wc) = o;
        return;
    }

    float icx3[4];
#pragma unroll
    for (int p = 0; p < 4; p++) icx3[p] = rcnt0(4 * j + p, 1);

    if (group == 1) {
        // ===== mf: vertical 3/7 sums into smem =====
        for (int idx = t; idx < 5 * NQ; idx += 256) {
            int chunk = idx / NQ;
            int qq = idx - chunk * NQ;
            int vr0 = chunk * 2;
            const float4* col = s_raw + qq;
            float4 r0 = col[(vr0+0)*QS], r1 = col[(vr0+1)*QS], r2 = col[(vr0+2)*QS],
                   r3 = col[(vr0+3)*QS], r4 = col[(vr0+4)*QS], r5 = col[(vr0+5)*QS],
                   r6 = col[(vr0+6)*QS], r7 = col[(vr0+7)*QS];
            float4 s3 = f4add(f4add(r2, r3), r4);
            float4 s7 = f4add(f4add(f4add(r0, r1), f4add(r5, r6)), s3);
            s_v3[vr0 * QS + qq] = s3;
            s_v7[vr0 * QS + qq] = s7;
            s3 = f4add(s3, f4sub(r5, r2));
            s7 = f4add(s7, f4sub(r7, r0));
            s_v3[(vr0 + 1) * QS + qq] = s3;
            s_v7[(vr0 + 1) * QS + qq] = s7;
        }
        __syncthreads();

        // ===== band-pass rows into s_raw slots 0..9 (edge quads already zero) =====
        float icx7[4];
#pragma unroll
        for (int p = 0; p < 4; p++) icx7[p] = rcnt0(4 * j + p, 3);
#pragma unroll
        for (int it = 0; it < 3; it++) {
            int vr = rc + it * 4;
            int vrr = (vr < VRS) ? vr : (VRS - 1);
            float4 a = s_v3[vrr * QS + q];
            float4 v7c = s_v7[vrr * QS + q];
            float l1 = __shfl_up_sync(FULLM, a.w, 4);
            float r1 = __shfl_down_sync(FULLM, a.x, 4);
            float L1 = __shfl_up_sync(FULLM, v7c.y, 4);
            float L2 = __shfl_up_sync(FULLM, v7c.z, 4);
            float L3 = __shfl_up_sync(FULLM, v7c.w, 4);
            float R1 = __shfl_down_sync(FULLM, v7c.x, 4);
            float R2 = __shfl_down_sync(FULLM, v7c.y, 4);
            float R3 = __shfl_down_sync(FULLM, v7c.z, 4);
            if (eL) {
                const float* p3 = (const float*)&s_v3[vrr * QS + q - 1];
                const float* p7 = (const float*)&s_v7[vrr * QS + q - 1];
                l1 = p3[3]; L1 = p7[1]; L2 = p7[2]; L3 = p7[3];
            }
            if (eR) {
                const float* p3 = (const float*)&s_v3[vrr * QS + q + 1];
                const float* p7 = (const float*)&s_v7[vrr * QS + q + 1];
                r1 = p3[0]; R1 = p7[0]; R2 = p7[1]; R3 = p7[2];
            }
            int g = rowBase + vr - 1;
            float iy3 = rcnt0(g, 1), iy7 = rcnt0(g, 3);
            float h3_0 = l1 + a.x + a.y;
            float h3_1 = a.x + a.y + a.z;
            float h3_2 = a.y + a.z + a.w;
            float h3_3 = a.z + a.w + r1;
            float h7_0 = L1 + L2 + L3 + v7c.x + v7c.y + v7c.z + v7c.w;
            float h7_1 = h7_0 - L1 + R1;
            float h7_2 = h7_1 - L2 + R2;
            float h7_3 = h7_2 - L3 + R3;
            float4 o;
            o.x = h3_0 * (icx3[0] * iy3) - h7_0 * (icx7[0] * iy7);
            o.y = h3_1 * (icx3[1] * iy3) - h7_1 * (icx7[1] * iy7);
            o.z = h3_2 * (icx3[2] * iy3) - h7_2 * (icx7[2] * iy7);
            o.w = h3_3 * (icx3[3] * iy3) - h7_3 * (icx7[3] * iy7);
            if (vr < VRS) s_raw[vr * QS + q] = o;
        }
        __syncthreads();
        conv3_shfl(s_raw, 2 * rc, q, eL, eR, s_w, inv, shft, outp, gyOut);
        return;
    }

    // ===== hf: fused vertical-3 + high-pass into s_v3 =====
#pragma unroll
    for (int it = 0; it < 3; it++) {
        int vr = rc + it * 4;
        int vrr = (vr < VRS) ? vr : (VRS - 1);
        const float4* rp = s_raw + (vrr + 2) * QS + q;
        float4 r2 = rp[0], r3 = rp[QS], r4 = rp[2 * QS];
        float4 v3c = f4add(f4add(r2, r3), r4);
        float l1 = __shfl_up_sync(FULLM, v3c.w, 4);
        float r1 = __shfl_down_sync(FULLM, v3c.x, 4);
        if (eL) {
            const float* p0 = (const float*)(rp - 1);
            l1 = p0[3] + p0[QS * 4 + 3] + p0[QS * 8 + 3];
        }
        if (eR) {
            const float* p0 = (const float*)(rp + 1);
            r1 = p0[0] + p0[QS * 4] + p0[QS * 8];
        }
        int g = rowBase + vr - 1;
        float iy3 = rcnt0(g, 1);
        float h3_0 = l1 + v3c.x + v3c.y;
        float h3_1 = v3c.x + v3c.y + v3c.z;
        float h3_2 = v3c.y + v3c.z + v3c.w;
        float h3_3 = v3c.z + v3c.w + r1;
        float4 o;
        o.x = r3.x - h3_0 * (icx3[0] * iy3);
        o.y = r3.y - h3_1 * (icx3[1] * iy3);
        o.z = r3.z - h3_2 * (icx3[2] * iy3);
        o.w = r3.w - h3_3 * (icx3[3] * iy3);
        if (vr < VRS) s_v3[vr * QS + q] = o;
    }
    if (t < 2 * VRS) {   // zero hp-buffer halo quads
        int vr = t % VRS;
        int qe = (t < VRS) ? 0 : 65;
        s_v3[vr * QS + qe] = make_float4(0.f, 0.f, 0.f, 0.f);
    }
    __syncthreads();
    conv3_shfl(s_v3, 2 * rc, q, eL, eR, s_w, inv, shft, outp, gyOut);
}

extern "C" void kernel_launch(void* const* d_in, const int* in_sizes, int n_in,
                              void* d_out, int out_size) {
    (void)in_sizes; (void)n_in; (void)out_size;
    dim3 grid(Hc / TH, Cc, Bc);
    dim3 block(256);
    trifreq_kernel<<<grid, block>>>(
        (const float*)d_in[0], (const float*)d_in[1], (const float*)d_in[2],
        (const float*)d_in[3], (const float*)d_in[4], (const float*)d_in[5],
        (const float*)d_in[6], (const float*)d_in[7], (float*)d_out);
}

// round 7
// speedup vs baseline: 1.1055x; 1.1055x over previous
#include <cuda_runtime.h>

#define Bc 8
#define Cc 96
#define Hc 256
#define Wc 256
#define TH 8
#define RROWS 16               // raw rows: img rowBase-4 .. rowBase+11 (slot s = imgrow-rowBase+4)
#define VRS 10                 // vsum rows: bp/hp rows img rowBase-1 .. rowBase+8 (vr = g-rowBase+1)
#define NQ 66
#define QS 67

__device__ __forceinline__ float4 f4add(float4 a, float4 b) {
    return make_float4(a.x+b.x, a.y+b.y, a.z+b.z, a.w+b.w);
}
__device__ __forceinline__ float4 f4sub(float4 a, float4 b) {
    return make_float4(a.x-b.x, a.y-b.y, a.z-b.z, a.w-b.w);
}

// reciprocal of valid-count for avgpool (count_include_pad=False); 0 outside image
__device__ __forceinline__ float rcnt0(int i, int p) {
    if (i < 0 || i > Hc - 1) return 0.f;
    int lo = i - p; if (lo < 0) lo = 0;
    int hi = i + p; if (hi > Hc - 1) hi = Hc - 1;
    return __fdividef(1.f, (float)(hi - lo + 1));
}

__device__ __forceinline__ float bn_silu(float acc, float scal, float shft) {
    float v = fmaf(acc, scal, shft);
    return v * __fdividef(1.f, 1.f + __expf(-v));
}

// 3 consecutive quads -> 12 floats (img cols 4j-4 .. 4j+7 when base = buf + vr*QS + j)
__device__ __forceinline__ void ld12(const float4* __restrict__ p, float* __restrict__ d) {
    float4 A = p[0], B = p[1], C = p[2];
    d[0]=A.x; d[1]=A.y; d[2]=A.z;  d[3]=A.w;
    d[4]=B.x; d[5]=B.y; d[6]=B.z;  d[7]=B.w;
    d[8]=C.x; d[9]=C.y; d[10]=C.z; d[11]=C.w;
}

__global__ __launch_bounds__(256, 5) void trifreq_kernel(
    const float* __restrict__ x,
    const float* __restrict__ w_lo,
    const float* __restrict__ w_mf,
    const float* __restrict__ w_hf,
    const float* __restrict__ bn_gamma,
    const float* __restrict__ bn_beta,
    const float* __restrict__ bn_mean,
    const float* __restrict__ bn_var,
    float* __restrict__ out)
{
    __shared__ float4 s_raw[RROWS * QS];
    __shared__ float4 s_v3[VRS * QS];    // vertical 3-sums
    __shared__ float4 s_v7[VRS * QS];    // vertical 7-sums (mf only)
    __shared__ float s_w[25];

    const int t = threadIdx.x;
    const int tileY = blockIdx.x;
    const int ch = blockIdx.y;
    const int b = blockIdx.z;
    const int group = ch >> 5;
    const int k = ch & 31;
    const int rowBase = tileY * TH;

    if (group == 0)      { if (t < 25) s_w[t] = w_lo[k * 25 + t]; }
    else if (group == 1) { if (t < 9)  s_w[t] = w_mf[k * 9 + t]; }
    else                 { if (t < 9)  s_w[t] = w_hf[k * 9 + t]; }

    // ---- raw tile load (zero outside image) ----
    const float* xp = x + (size_t)(b * Cc + ch) * Hc * Wc;
    const int rlo = (group == 0) ? 2 : 0;
    const int rhi = (group == 0) ? 14 : 16;
    const int nload = (rhi - rlo) * NQ;
    for (int idx = t; idx < nload; idx += 256) {
        int rr = idx / NQ + rlo;
        int qq = idx - (rr - rlo) * NQ;
        int gr = rowBase + rr - 4;
        float4 v = make_float4(0.f, 0.f, 0.f, 0.f);
        if (qq >= 1 && qq <= 64 && (unsigned)gr < (unsigned)Hc)
            v = *(const float4*)(xp + gr * Wc + (qq - 1) * 4);
        s_raw[rr * QS + qq] = v;
    }
    __syncthreads();

    const int oc = 3 * k + group;                 // channel shuffle folded in
    const float inv  = bn_gamma[oc] * rsqrtf(bn_var[oc] + 1e-5f);
    const float shft = bn_beta[oc] - bn_mean[oc] * inv;

    const int j = t & 63;                         // quad: output cols 4j..4j+3
    const int rc = t >> 6;                        // 2-row band
    const int gy0 = rowBase + 2 * rc;             // output rows gy0, gy0+1
    float* outp = out + (size_t)(b * Cc + oc) * Hc * Wc + j * 4;

    if (group == 0) {
        // ===== lo: 5x5 dwconv, single-pass scatter over 6 raw rows =====
        float a0[4] = {0.f,0.f,0.f,0.f}, a1[4] = {0.f,0.f,0.f,0.f};
#pragma unroll
        for (int rrow = 0; rrow < 6; rrow++) {
            float u[12];
            ld12(s_raw + (2 * rc + 2 + rrow) * QS + j, u);   // img row gy0-2+rrow
            if (rrow < 5) {
#pragma unroll
                for (int kc = 0; kc < 5; kc++) {
                    float wv = s_w[rrow * 5 + kc];
#pragma unroll
                    for (int p = 0; p < 4; p++) a0[p] = fmaf(wv, u[p + kc + 2], a0[p]);
                }
            }
            if (rrow >= 1) {
#pragma unroll
                for (int kc = 0; kc < 5; kc++) {
                    float wv = s_w[(rrow - 1) * 5 + kc];
#pragma unroll
                    for (int p = 0; p < 4; p++) a1[p] = fmaf(wv, u[p + kc + 2], a1[p]);
                }
            }
        }
        float4 o;
        o.x = bn_silu(a0[0], inv, shft); o.y = bn_silu(a0[1], inv, shft);
        o.z = bn_silu(a0[2], inv, shft); o.w = bn_silu(a0[3], inv, shft);
        *(float4*)(outp + (size_t)gy0 * Wc) = o;
        o.x = bn_silu(a1[0], inv, shft); o.y = bn_silu(a1[1], inv, shft);
        o.z = bn_silu(a1[2], inv, shft); o.w = bn_silu(a1[3], inv, shft);
        *(float4*)(outp + (size_t)(gy0 + 1) * Wc) = o;
        return;
    }

    float icx3[6];
#pragma unroll
    for (int m = 0; m < 6; m++) icx3[m] = rcnt0(4 * j - 1 + m, 1);

    if (group == 1) {
        // ===== mf: vertical 3/7 sums into smem (chunks of 2 rows) =====
        for (int idx = t; idx < 5 * NQ; idx += 256) {
            int chunk = idx / NQ;
            int qq = idx - chunk * NQ;
            int vr0 = chunk * 2;
            const float4* col = s_raw + qq;
            float4 r0 = col[(vr0+0)*QS], r1 = col[(vr0+1)*QS], r2 = col[(vr0+2)*QS],
                   r3 = col[(vr0+3)*QS], r4 = col[(vr0+4)*QS], r5 = col[(vr0+5)*QS],
                   r6 = col[(vr0+6)*QS], r7 = col[(vr0+7)*QS];
            float4 s3 = f4add(f4add(r2, r3), r4);
            float4 s7 = f4add(f4add(f4add(r0, r1), f4add(r5, r6)), s3);
            s_v3[vr0 * QS + qq] = s3;
            s_v7[vr0 * QS + qq] = s7;
            s3 = f4add(s3, f4sub(r5, r2));
            s7 = f4add(s7, f4sub(r7, r0));
            s_v3[(vr0 + 1) * QS + qq] = s3;
            s_v7[(vr0 + 1) * QS + qq] = s7;
        }
        __syncthreads();

        // ===== fused band-pass + 3x3 conv scatter (no bp buffer, no extra sync) =====
        float icx7[6];
#pragma unroll
        for (int m = 0; m < 6; m++) icx7[m] = rcnt0(4 * j - 1 + m, 3);
        float a0[4] = {0.f,0.f,0.f,0.f}, a1[4] = {0.f,0.f,0.f,0.f};
#pragma unroll
        for (int rrow = 0; rrow < 4; rrow++) {
            int vr = 2 * rc + rrow;               // bp row g = gy0-1+rrow
            int g = gy0 - 1 + rrow;
            float iy3 = rcnt0(g, 1), iy7 = rcnt0(g, 3);
            float bp[6];
            {
                float u[12];
                ld12(s_v3 + vr * QS + j, u);      // v3 cols 4j-4..4j+7
                float h = u[2] + u[3] + u[4];     // h3 for bp col 4j-1
                bp[0] = h * (icx3[0] * iy3);
#pragma unroll
                for (int m = 1; m < 6; m++) {
                    h += u[m + 4] - u[m + 1];
                    bp[m] = h * (icx3[m] * iy3);
                }
            }
            {
                float u[12];
                ld12(s_v7 + vr * QS + j, u);      // v7 cols 4j-4..4j+7
                float h = u[0]+u[1]+u[2]+u[3]+u[4]+u[5]+u[6];   // h7 for bp col 4j-1
                bp[0] -= h * (icx7[0] * iy7);
#pragma unroll
                for (int m = 1; m < 6; m++) {
                    h += u[m + 6] - u[m - 1];
                    bp[m] -= h * (icx7[m] * iy7);
                }
            }
            if (rrow < 3) {
#pragma unroll
                for (int kc = 0; kc < 3; kc++) {
                    float wv = s_w[rrow * 3 + kc];
#pragma unroll
                    for (int p = 0; p < 4; p++) a0[p] = fmaf(wv, bp[p + kc], a0[p]);
                }
            }
            if (rrow >= 1) {
#pragma unroll
                for (int kc = 0; kc < 3; kc++) {
                    float wv = s_w[(rrow - 1) * 3 + kc];
#pragma unroll
                    for (int p = 0; p < 4; p++) a1[p] = fmaf(wv, bp[p + kc], a1[p]);
                }
            }
        }
        float4 o;
        o.x = bn_silu(a0[0], inv, shft); o.y = bn_silu(a0[1], inv, shft);
        o.z = bn_silu(a0[2], inv, shft); o.w = bn_silu(a0[3], inv, shft);
        *(float4*)(outp + (size_t)gy0 * Wc) = o;
        o.x = bn_silu(a1[0], inv, shft); o.y = bn_silu(a1[1], inv, shft);
        o.z = bn_silu(a1[2], inv, shft); o.w = bn_silu(a1[3], inv, shft);
        *(float4*)(outp + (size_t)(gy0 + 1) * Wc) = o;
        return;
    }

    // ===== hf: vertical 3-sums (chunks of 2 rows) =====
    for (int idx = t; idx < 5 * NQ; idx += 256) {
        int chunk = idx / NQ;
        int qq = idx - chunk * NQ;
        int vr0 = chunk * 2;
        const float4* col = s_raw + qq;
        float4 r2 = col[(vr0+2)*QS], r3 = col[(vr0+3)*QS],
               r4 = col[(vr0+4)*QS], r5 = col[(vr0+5)*QS];
        float4 s3 = f4add(f4add(r2, r3), r4);
        s_v3[vr0 * QS + qq] = s3;
        s3 = f4add(s3, f4sub(r5, r2));
        s_v3[(vr0 + 1) * QS + qq] = s3;
    }
    __syncthreads();

    // ===== fused high-pass + 3x3 conv scatter =====
    {
        float a0[4] = {0.f,0.f,0.f,0.f}, a1[4] = {0.f,0.f,0.f,0.f};
#pragma unroll
        for (int rrow = 0; rrow < 4; rrow++) {
            int vr = 2 * rc + rrow;               // hp row g = gy0-1+rrow
            int g = gy0 - 1 + rrow;
            float iy3 = rcnt0(g, 1);
            float hp[6];
            {
                float u[12], ur[12];
                ld12(s_v3 + vr * QS + j, u);              // v3 cols 4j-4..4j+7
                ld12(s_raw + (vr + 3) * QS + j, ur);      // raw row g, cols 4j-4..4j+7
                float h = u[2] + u[3] + u[4];             // h3 for col 4j-1
                hp[0] = ur[3] - h * (icx3[0] * iy3);
#pragma unroll
                for (int m = 1; m < 6; m++) {
                    h += u[m + 4] - u[m + 1];
                    hp[m] = ur[m + 3] - h * (icx3[m] * iy3);
                }
            }
            if (rrow < 3) {
#pragma unroll
                for (int kc = 0; kc < 3; kc++) {
                    float wv = s_w[rrow * 3 + kc];
#pragma unroll
                    for (int p = 0; p < 4; p++) a0[p] = fmaf(wv, hp[p + kc], a0[p]);
                }
            }
            if (rrow >= 1) {
#pragma unroll
                for (int kc = 0; kc < 3; kc++) {
                    float wv = s_w[(rrow - 1) * 3 + kc];
#pragma unroll
                    for (int p = 0; p < 4; p++) a1[p] = fmaf(wv, hp[p + kc], a1[p]);
                }
            }
        }
        float4 o;
        o.x = bn_silu(a0[0], inv, shft); o.y = bn_silu(a0[1], inv, shft);
        o.z = bn_silu(a0[2], inv, shft); o.w = bn_silu(a0[3], inv, shft);
        *(float4*)(outp + (size_t)gy0 * Wc) = o;
        o.x = bn_silu(a1[0], inv, shft); o.y = bn_silu(a1[1], inv, shft);
        o.z = bn_silu(a1[2], inv, shft); o.w = bn_silu(a1[3], inv, shft);
        *(float4*)(outp + (size_t)(gy0 + 1) * Wc) = o;
    }
}

extern "C" void kernel_launch(void* const* d_in, const int* in_sizes, int n_in,
                              void* d_out, int out_size) {
    (void)in_sizes; (void)n_in; (void)out_size;
    dim3 grid(Hc / TH, Cc, Bc);
    dim3 block(256);
    trifreq_kernel<<<grid, block>>>(
        (const float*)d_in[0], (const float*)d_in[1], (const float*)d_in[2],
        (const float*)d_in[3], (const float*)d_in[4], (const float*)d_in[5],
        (const float*)d_in[6], (const float*)d_in[7], (float*)d_out);
}